// round 2
// baseline (speedup 1.0000x reference)
#include <cuda_runtime.h>
#include <cuda_bf16.h>
#include <cstdint>
#include <math.h>

// ---------------------------------------------------------------------------
// Hybrid router. B*S = 16384 tokens, IN=2048, E=16, D=128, A=128, R=4, top_k=2.
//
// Reformulation (dyn is rank-4, attention folded into D):
//   ge = LN(expert_embedding); k[f,a] = sum_d ge[f,d] Wk[a,d]
//   Mk[f,d] = scale * sum_a k[f,a] Wq[a,d]
//   L[t,e,f] = rstd_t*( sum_r h_r T[e,f,r] + Tb[e,f] - mu_t*Gs[e,f] ) + Bs[e,f]
//   mu_t, var_t from rank-4 moments (S1, Q(4x4), C, S0, SSB).
// Main kernel: per token 20 dots of length 2048 vs hidden (Wv 16 + mlp_w1 4)
// using packed fp32x2 FMA, + tiny epilogue (softmaxes, top-2).
// ---------------------------------------------------------------------------

#define NTOK   16384
#define GRID   148
#define TPB    256

// tables: 7 tables [16 e][16 f] at stride 35 (conflict-free LDS)
#define TSTRIDE 35
#define TSIZE   544      // per table (15*35+15+1 rounded up)
__device__ float g_tab[7 * TSIZE];
__device__ float g_misc[26];   // 0..3 S1, 4..19 Q, 20..23 C, 24 S0, 25 SSB

// ---------------------------------------------------------------------------
__device__ __forceinline__ unsigned long long ffma2(unsigned long long a,
                                                    unsigned long long b,
                                                    unsigned long long c) {
    unsigned long long d;
    asm("fma.rn.f32x2 %0, %1, %2, %3;" : "=l"(d) : "l"(a), "l"(b), "l"(c));
    return d;
}
__device__ __forceinline__ float2 upk(unsigned long long v) {
    float2 f;
    asm("mov.b64 {%0, %1}, %2;" : "=f"(f.x), "=f"(f.y) : "l"(v));
    return f;
}

// ---------------------------------------------------------------------------
// Precompute kernel: 1 block, 1024 threads.
// ---------------------------------------------------------------------------
__global__ void __launch_bounds__(1024)
prep_kernel(const float* __restrict__ ee, const float* __restrict__ gamma,
            const float* __restrict__ beta, const float* __restrict__ w2,
            const float* __restrict__ b2, const float* __restrict__ wq,
            const float* __restrict__ wk)
{
    __shared__ float sge[2048];
    __shared__ float sk[2048];
    __shared__ float sMk[2048];
    __shared__ float sred[64];
    __shared__ float swp[32][26];

    int tid = threadIdx.x, lane = tid & 31, wid = tid >> 5;

    // --- LayerNorm of expert_embedding over all 2048 ---
    float a0 = ee[tid], a1 = ee[tid + 1024];
    float ls = a0 + a1, lq = a0 * a0 + a1 * a1;
    #pragma unroll
    for (int m = 16; m; m >>= 1) {
        ls += __shfl_xor_sync(~0u, ls, m);
        lq += __shfl_xor_sync(~0u, lq, m);
    }
    if (lane == 0) { sred[wid] = ls; sred[32 + wid] = lq; }
    __syncthreads();
    if (tid == 0) {
        float s = 0.f, q = 0.f;
        for (int i = 0; i < 32; i++) { s += sred[i]; q += sred[32 + i]; }
        float mu = s * (1.0f / 2048.0f);
        float var = q * (1.0f / 2048.0f) - mu * mu;
        sred[0] = mu; sred[1] = rsqrtf(var + 1e-5f);
    }
    __syncthreads();
    {
        float mu = sred[0], rs = sred[1];
        sge[tid]        = (a0 - mu) * rs * gamma[tid]        + beta[tid];
        sge[tid + 1024] = (a1 - mu) * rs * gamma[tid + 1024] + beta[tid + 1024];
    }
    __syncthreads();

    // --- k[f][a] = sum_d ge[f,d] * Wk[a,d] ---
    for (int idx = tid; idx < 2048; idx += 1024) {
        int f = idx >> 7, a = idx & 127;
        const float* gp = sge + f * 128;
        const float* wp = wk + a * 128;
        float acc = 0.f;
        #pragma unroll 8
        for (int d = 0; d < 128; d++) acc = fmaf(gp[d], wp[d], acc);
        sk[f * 128 + a] = acc;
    }
    __syncthreads();

    // --- Mk[f][d] = scale * sum_a k[f,a] * Wq[a,d] ---
    {
        const float scale = 0.08838834764831845f;  // 1/sqrt(128)
        for (int idx = tid; idx < 2048; idx += 1024) {
            int f = idx >> 7, d = idx & 127;
            const float* kp = sk + f * 128;
            float acc = 0.f;
            #pragma unroll 8
            for (int a = 0; a < 128; a++) acc = fmaf(kp[a], wq[a * 128 + d], acc);
            sMk[f * 128 + d] = acc * scale;
        }
    }
    __syncthreads();

    // --- tables T0..T3, Tb, Gs, Bs per (e,f); 4 threads per pair ---
    {
        int pr = tid >> 2, part = tid & 3;
        int e = pr >> 4, f = pr & 15;
        float t0 = 0, t1 = 0, t2 = 0, t3 = 0, tb = 0, gs = 0, bs = 0;
        int d0 = part * 32;
        for (int dd = 0; dd < 32; dd++) {
            int d = d0 + dd;
            int o = e * 128 + d;
            float mk = sMk[f * 128 + d];
            float m = mk * gamma[o];
            const float* w4 = w2 + o * 4;
            t0 = fmaf(w4[0], m, t0);
            t1 = fmaf(w4[1], m, t1);
            t2 = fmaf(w4[2], m, t2);
            t3 = fmaf(w4[3], m, t3);
            tb = fmaf(b2[o], m, tb);
            gs += m;
            bs = fmaf(beta[o], mk, bs);
        }
        #pragma unroll
        for (int m = 1; m < 4; m <<= 1) {
            t0 += __shfl_xor_sync(~0u, t0, m);
            t1 += __shfl_xor_sync(~0u, t1, m);
            t2 += __shfl_xor_sync(~0u, t2, m);
            t3 += __shfl_xor_sync(~0u, t3, m);
            tb += __shfl_xor_sync(~0u, tb, m);
            gs += __shfl_xor_sync(~0u, gs, m);
            bs += __shfl_xor_sync(~0u, bs, m);
        }
        if (part == 0) {
            int o = e * TSTRIDE + f;
            g_tab[0 * TSIZE + o] = t0;
            g_tab[1 * TSIZE + o] = t1;
            g_tab[2 * TSIZE + o] = t2;
            g_tab[3 * TSIZE + o] = t3;
            g_tab[4 * TSIZE + o] = tb;
            g_tab[5 * TSIZE + o] = gs;
            g_tab[6 * TSIZE + o] = bs;
        }
    }
    __syncthreads();

    // --- scalar moments of dyn: S1[4], Q[16], C[4], S0, SSB ---
    {
        float p[26];
        #pragma unroll
        for (int q = 0; q < 26; q++) p[q] = 0.f;
        #pragma unroll
        for (int k2 = 0; k2 < 2; k2++) {
            int o = tid * 2 + k2;
            const float* w4 = w2 + o * 4;
            float b = b2[o];
            float w0 = w4[0], w1 = w4[1], w2v = w4[2], w3 = w4[3];
            p[0] += w0; p[1] += w1; p[2] += w2v; p[3] += w3;
            p[4]  += w0 * w0; p[5]  += w0 * w1; p[6]  += w0 * w2v; p[7]  += w0 * w3;
            p[8]  += w1 * w0; p[9]  += w1 * w1; p[10] += w1 * w2v; p[11] += w1 * w3;
            p[12] += w2v * w0; p[13] += w2v * w1; p[14] += w2v * w2v; p[15] += w2v * w3;
            p[16] += w3 * w0; p[17] += w3 * w1; p[18] += w3 * w2v; p[19] += w3 * w3;
            p[20] += w0 * b; p[21] += w1 * b; p[22] += w2v * b; p[23] += w3 * b;
            p[24] += b; p[25] += b * b;
        }
        #pragma unroll
        for (int m = 16; m; m >>= 1) {
            #pragma unroll
            for (int q = 0; q < 26; q++) p[q] += __shfl_xor_sync(~0u, p[q], m);
        }
        if (lane == 0) {
            #pragma unroll
            for (int q = 0; q < 26; q++) swp[wid][q] = p[q];
        }
    }
    __syncthreads();
    if (tid < 26) {
        float s = 0.f;
        for (int w = 0; w < 32; w++) s += swp[w][tid];
        g_misc[tid] = s;
    }
}

// ---------------------------------------------------------------------------
// Main kernel: 148 blocks x 256 threads, ~200 KB dynamic smem.
// smem: sw[20*2048] | stab[7*544] | spart[8*720] | sfin[8*84] | smisc[48]
// ---------------------------------------------------------------------------
#define SW_F    40960
#define STAB_F  (7 * TSIZE)
#define SPART_F (8 * 720)
#define SFIN_F  (8 * 84)
#define SMISC_F 48
#define SMEM_FLOATS (SW_F + STAB_F + SPART_F + SFIN_F + SMISC_F)
#define SMEM_BYTES  (SMEM_FLOATS * 4)

__global__ void __launch_bounds__(TPB, 1)
main_kernel(const float* __restrict__ hidden, const float* __restrict__ wv_w,
            const float* __restrict__ wv_b, const float* __restrict__ w1,
            const float* __restrict__ b1, float* __restrict__ out)
{
    extern __shared__ float smem[];
    float* sw    = smem;
    float* stab  = sw + SW_F;
    float* spart = stab + STAB_F;
    float* sfin  = spart + SPART_F;
    float* smisc = sfin + SFIN_F;

    int tid = threadIdx.x, lane = tid & 31, warp = tid >> 5;

    // cooperative smem fill
    for (int idx = tid; idx < 8192; idx += TPB)
        ((float4*)sw)[idx] = ((const float4*)wv_w)[idx];
    for (int idx = tid; idx < 2048; idx += TPB)
        ((float4*)sw)[8192 + idx] = ((const float4*)w1)[idx];
    for (int idx = tid; idx < STAB_F; idx += TPB)
        stab[idx] = g_tab[idx];
    if (tid < 26) smisc[tid] = g_misc[tid];
    if (tid < 4)  smisc[26 + tid] = b1[tid];
    if (tid < 16) smisc[30 + tid] = wv_b[tid];
    __syncthreads();

    int start = (int)(((long long)blockIdx.x * NTOK) / GRID);
    int end   = (int)(((long long)(blockIdx.x + 1) * NTOK) / GRID);

    float* part = spart + warp * 720;
    float* sfw  = sfin + warp * 84;

    for (int t0 = start + warp * 4; t0 < end; t0 += 32) {
        // token pointers (clamp invalid to t0)
        const ulonglong2* hp[4];
        #pragma unroll
        for (int i = 0; i < 4; i++) {
            int tt = t0 + i;
            int tu = (tt < end) ? tt : t0;
            hp[i] = (const ulonglong2*)(hidden + (size_t)tu * 2048);
        }

        unsigned long long acc[20][4];
        #pragma unroll
        for (int r = 0; r < 20; r++)
            #pragma unroll
            for (int i = 0; i < 4; i++) acc[r][i] = 0ull;

        ulonglong2 nhv[4];
        #pragma unroll
        for (int i = 0; i < 4; i++) nhv[i] = hp[i][lane];

        #pragma unroll 1
        for (int j = 0; j < 16; j++) {
            ulonglong2 hv[4];
            #pragma unroll
            for (int i = 0; i < 4; i++) hv[i] = nhv[i];
            int jn = (j < 15) ? (j + 1) : 15;
            #pragma unroll
            for (int i = 0; i < 4; i++) nhv[i] = hp[i][jn * 32 + lane];

            const ulonglong2* wrow = ((const ulonglong2*)sw) + j * 32 + lane;
            #pragma unroll
            for (int r = 0; r < 20; r++) {
                ulonglong2 wv = wrow[r * 512];
                #pragma unroll
                for (int i = 0; i < 4; i++) {
                    acc[r][i] = ffma2(hv[i].x, wv.x, acc[r][i]);
                    acc[r][i] = ffma2(hv[i].y, wv.y, acc[r][i]);
                }
            }
        }

        // --- chunked smem-transpose reduction: 4 chunks of 5 rows ---
        #pragma unroll
        for (int c = 0; c < 4; c++) {
            #pragma unroll
            for (int rl = 0; rl < 5; rl++) {
                #pragma unroll
                for (int i = 0; i < 4; i++) {
                    float2 f = upk(acc[c * 5 + rl][i]);
                    part[(rl * 4 + i) * 36 + lane] = f.x + f.y;
                }
            }
            __syncwarp();
            if (lane < 20) {
                const float4* p4 = (const float4*)(part + lane * 36);
                float4 q0 = p4[0], q1 = p4[1], q2 = p4[2], q3 = p4[3];
                float4 q4 = p4[4], q5 = p4[5], q6 = p4[6], q7 = p4[7];
                float s = ((q0.x + q0.y) + (q0.z + q0.w)) + ((q1.x + q1.y) + (q1.z + q1.w))
                        + ((q2.x + q2.y) + (q2.z + q2.w)) + ((q3.x + q3.y) + (q3.z + q3.w))
                        + ((q4.x + q4.y) + (q4.z + q4.w)) + ((q5.x + q5.y) + (q5.z + q5.w))
                        + ((q6.x + q6.y) + (q6.z + q6.w)) + ((q7.x + q7.y) + (q7.z + q7.w));
                sfw[(lane & 3) * 21 + c * 5 + (lane >> 2)] = s;
            }
            __syncwarp();
        }

        // --- epilogue: lanes (2e+h), h half of f range ---
        int e  = lane >> 1;
        int fb = (lane & 1) << 3;
        const float* tb0 = stab + e * TSTRIDE + fb;

        #pragma unroll 1
        for (int i = 0; i < 4; i++) {
            if (t0 + i >= end) break;
            const float* sf = sfw + i * 21;
            float h0 = fmaxf(sf[16] + smisc[26], 0.f);
            float h1 = fmaxf(sf[17] + smisc[27], 0.f);
            float h2 = fmaxf(sf[18] + smisc[28], 0.f);
            float h3 = fmaxf(sf[19] + smisc[29], 0.f);
            float mu = (h0 * smisc[0] + h1 * smisc[1] + h2 * smisc[2] + h3 * smisc[3]
                        + smisc[24]) * (1.f / 2048.f);
            const float* Q = smisc + 4;
            float ex = smisc[25]
                     + 2.f * (h0 * smisc[20] + h1 * smisc[21] + h2 * smisc[22] + h3 * smisc[23])
                     + h0 * (h0 * Q[0]  + h1 * Q[1]  + h2 * Q[2]  + h3 * Q[3])
                     + h1 * (h0 * Q[4]  + h1 * Q[5]  + h2 * Q[6]  + h3 * Q[7])
                     + h2 * (h0 * Q[8]  + h1 * Q[9]  + h2 * Q[10] + h3 * Q[11])
                     + h3 * (h0 * Q[12] + h1 * Q[13] + h2 * Q[14] + h3 * Q[15]);
            ex *= (1.f / 2048.f);
            float rstd = rsqrtf(ex - mu * mu + 1e-5f);

            float Lv[8];
            float Lmax = -1e30f;
            #pragma unroll
            for (int ff = 0; ff < 8; ff++) {
                float a = tb0[4 * TSIZE + ff];                 // Tb
                a = fmaf(h0, tb0[0 * TSIZE + ff], a);
                a = fmaf(h1, tb0[1 * TSIZE + ff], a);
                a = fmaf(h2, tb0[2 * TSIZE + ff], a);
                a = fmaf(h3, tb0[3 * TSIZE + ff], a);
                a = fmaf(-mu, tb0[5 * TSIZE + ff], a);         // Gs
                float L = fmaf(rstd, a, tb0[6 * TSIZE + ff]);  // Bs
                Lv[ff] = L;
                Lmax = fmaxf(Lmax, L);
            }
            Lmax = fmaxf(Lmax, __shfl_xor_sync(~0u, Lmax, 1));
            float se = 0.f, gd = 0.f;
            #pragma unroll
            for (int ff = 0; ff < 8; ff++) {
                float p = __expf(Lv[ff] - Lmax);
                se += p;
                gd = fmaf(p, sf[fb + ff] + smisc[30 + fb + ff], gd);
            }
            se += __shfl_xor_sync(~0u, se, 1);
            gd += __shfl_xor_sync(~0u, gd, 1);
            float gate = gd / se;

            // rw = softmax over e (parity-preserving butterfly, strides 2..16)
            float gmax = gate;
            #pragma unroll
            for (int m = 2; m <= 16; m <<= 1)
                gmax = fmaxf(gmax, __shfl_xor_sync(~0u, gmax, m));
            float er = __expf(gate - gmax);
            float es = er;
            #pragma unroll
            for (int m = 2; m <= 16; m <<= 1)
                es += __shfl_xor_sync(~0u, es, m);
            float rw = er / es;

            // top-2 over e with index tie-break (lower index wins)
            float v1 = rw, v2 = -1.f;
            int i1 = e, i2 = 16;
            #pragma unroll
            for (int m = 2; m <= 16; m <<= 1) {
                float ov1 = __shfl_xor_sync(~0u, v1, m);
                int   oi1 = __shfl_xor_sync(~0u, i1, m);
                float ov2 = __shfl_xor_sync(~0u, v2, m);
                int   oi2 = __shfl_xor_sync(~0u, i2, m);
                bool fw = (v1 > ov1) || (v1 == ov1 && i1 < oi1);
                float w1v = fw ? v1 : ov1;  int w1i = fw ? i1 : oi1;
                float l1v = fw ? ov1 : v1;  int l1i = fw ? oi1 : i1;
                float c2v = fw ? v2 : ov2;  int c2i = fw ? i2 : oi2;
                bool sv = (l1v > c2v) || (l1v == c2v && l1i < c2i);
                v1 = w1v; i1 = w1i;
                v2 = sv ? l1v : c2v;
                i2 = sv ? l1i : c2i;
            }

            float texp = __expf((v2 - v1) * 10.f);
            float inv = 1.f / (1.f + texp);
            float ov = (e == i1) ? inv : ((e == i2) ? texp * inv : 0.f);
            if (!(lane & 1)) out[(size_t)(t0 + i) * 16 + e] = ov;
        }
    }
}

// ---------------------------------------------------------------------------
extern "C" void kernel_launch(void* const* d_in, const int* in_sizes, int n_in,
                              void* d_out, int out_size)
{
    const float* hidden = (const float*)d_in[0];
    const float* ee     = (const float*)d_in[1];
    const float* gamma  = (const float*)d_in[2];
    const float* beta   = (const float*)d_in[3];
    const float* wv_w   = (const float*)d_in[4];
    const float* wv_b   = (const float*)d_in[5];
    const float* w1     = (const float*)d_in[6];
    const float* b1     = (const float*)d_in[7];
    const float* w2     = (const float*)d_in[8];
    const float* b2     = (const float*)d_in[9];
    const float* wq     = (const float*)d_in[10];
    const float* wk     = (const float*)d_in[11];
    float* out = (float*)d_out;

    cudaFuncSetAttribute(main_kernel, cudaFuncAttributeMaxDynamicSharedMemorySize,
                         SMEM_BYTES);

    prep_kernel<<<1, 1024>>>(ee, gamma, beta, w2, b2, wq, wk);
    main_kernel<<<GRID, TPB, SMEM_BYTES>>>(hidden, wv_w, wv_b, w1, b1, out);
}

// round 3
// speedup vs baseline: 1.6684x; 1.6684x over previous
#include <cuda_runtime.h>
#include <cstdint>
#include <math.h>

// ---------------------------------------------------------------------------
// Hybrid router. B*S = 16384 tokens, IN=2048, E=16, D=128, A=128, R=4, top_k=2.
// Single fused kernel. Each block redundantly computes the tiny precompute
// (LN(ee) -> k -> Mk -> tables + rank-4 moments) into its own smem (~4us,
// parallel on all SMs), then streams tokens: 20 dots of length 2048 per token
// (16 Wv rows + 4 mlp_w1 rows) with packed fp32x2 FMA, hidden double-buffered
// via cp.async (zero register cost), then a tiny per-token epilogue.
// ---------------------------------------------------------------------------

#define NTOK 16384
#define GRID 148
#define TPB  256

#define TSTRIDE 35
#define TSIZE   544

// smem layout (floats)
#define SW_F       40960          // 20 rows x 2048 weights
#define STAB_F     (7 * TSIZE)    // 3808
#define SMISC_F    64
#define SFIN_F     (8 * 84)       // 672
#define SUNION_F   (8 * 1024)     // per-warp: hidden double-buffer / reduce scratch
#define OFF_STAB   SW_F
#define OFF_SMISC  (OFF_STAB + STAB_F)
#define OFF_SFIN   (OFF_SMISC + SMISC_F)
#define OFF_SUNION (OFF_SFIN + SFIN_F)
#define SMEM_FLOATS (OFF_SUNION + SUNION_F)
#define SMEM_BYTES  (SMEM_FLOATS * 4)

// ---------------------------------------------------------------------------
__device__ __forceinline__ unsigned long long ffma2(unsigned long long a,
                                                    unsigned long long b,
                                                    unsigned long long c) {
    unsigned long long d;
    asm("fma.rn.f32x2 %0, %1, %2, %3;" : "=l"(d) : "l"(a), "l"(b), "l"(c));
    return d;
}
__device__ __forceinline__ float2 upk(unsigned long long v) {
    float2 f;
    asm("mov.b64 {%0, %1}, %2;" : "=f"(f.x), "=f"(f.y) : "l"(v));
    return f;
}
__device__ __forceinline__ void cpa16(uint32_t dst, const void* src) {
    asm volatile("cp.async.cg.shared.global [%0], [%1], 16;"
                 :: "r"(dst), "l"(src));
}
__device__ __forceinline__ void cpa_commit() {
    asm volatile("cp.async.commit_group;");
}
template <int N>
__device__ __forceinline__ void cpa_wait() {
    asm volatile("cp.async.wait_group %0;" :: "n"(N));
}
__device__ __forceinline__ float wred(float v) {
    #pragma unroll
    for (int m = 16; m; m >>= 1) v += __shfl_xor_sync(~0u, v, m);
    return v;
}

// ---------------------------------------------------------------------------
__global__ void __launch_bounds__(TPB, 1)
fused_kernel(const float* __restrict__ hidden, const float* __restrict__ ee,
             const float* __restrict__ gamma, const float* __restrict__ beta,
             const float* __restrict__ wv_w, const float* __restrict__ wv_b,
             const float* __restrict__ w1, const float* __restrict__ b1,
             const float* __restrict__ w2, const float* __restrict__ b2,
             const float* __restrict__ wq, const float* __restrict__ wk,
             float* __restrict__ out)
{
    extern __shared__ float smem[];
    float* sw     = smem;
    float* stab   = smem + OFF_STAB;
    float* smisc  = smem + OFF_SMISC;
    float* sfin   = smem + OFF_SFIN;
    float* sunion = smem + OFF_SUNION;

    int tid = threadIdx.x, lane = tid & 31, warp = tid >> 5;

    // ===================== stage 0: weights -> smem =====================
    for (int idx = tid; idx < 8192; idx += TPB)
        ((float4*)sw)[idx] = ((const float4*)wv_w)[idx];
    for (int idx = tid; idx < 2048; idx += TPB)
        ((float4*)sw)[8192 + idx] = ((const float4*)w1)[idx];

    // ===================== stage 1: per-block precompute =====================
    float* sge = sunion;          // 2048
    float* sk_ = sunion + 2048;   // 2048
    float* sMk = sunion + 4096;   // 2048
    float* sred = sfin;           // temp reduce scratch (re-used later as sfw)

    // --- LN of expert_embedding over 2048 ---
    {
        float ev[8];
        float ls = 0.f, lq = 0.f;
        #pragma unroll
        for (int k = 0; k < 8; k++) {
            float v = ee[tid + k * 256];
            ev[k] = v; ls += v; lq += v * v;
        }
        ls = wred(ls); lq = wred(lq);
        if (lane == 0) { sred[warp] = ls; sred[8 + warp] = lq; }
        __syncthreads();
        if (tid == 0) {
            float s = 0.f, q = 0.f;
            for (int i = 0; i < 8; i++) { s += sred[i]; q += sred[8 + i]; }
            float mu = s * (1.0f / 2048.0f);
            float var = q * (1.0f / 2048.0f) - mu * mu;
            sred[16] = mu; sred[17] = rsqrtf(var + 1e-5f);
        }
        __syncthreads();
        float mu = sred[16], rs = sred[17];
        #pragma unroll
        for (int k = 0; k < 8; k++) {
            int i = tid + k * 256;
            sge[i] = (ev[k] - mu) * rs * gamma[i] + beta[i];
        }
        __syncthreads();
    }

    // --- k[f][a] = sum_d ge[f,d] * Wk[a,d] (warp-reduce per output) ---
    #pragma unroll 4
    for (int o = warp; o < 2048; o += 8) {
        int f = o >> 7, a = o & 127;
        float4 g = ((const float4*)(sge + f * 128))[lane];
        float4 w = ((const float4*)(wk + a * 128))[lane];
        float p = fmaf(g.x, w.x, fmaf(g.y, w.y, fmaf(g.z, w.z, g.w * w.w)));
        p = wred(p);
        if (lane == 0) sk_[f * 128 + a] = p;
    }
    __syncthreads();

    // --- Mk[f][d] = scale * sum_a k[f,a]*Wq[a,d] (lane=d, coalesced wq) ---
    for (int task = warp; task < 64; task += 8) {
        int f = task >> 2, d = (task & 3) * 32 + lane;
        const float* kf = sk_ + f * 128;
        float a0 = 0.f, a1 = 0.f;
        #pragma unroll 8
        for (int a = 0; a < 128; a += 2) {
            a0 = fmaf(kf[a],     wq[a * 128 + d],       a0);
            a1 = fmaf(kf[a + 1], wq[(a + 1) * 128 + d], a1);
        }
        sMk[f * 128 + d] = (a0 + a1) * 0.08838834764831845f;  // 1/sqrt(128)
    }
    __syncthreads();

    // --- tables T0..T3, Tb, Gs, Bs per (e,f): one warp per pair ---
    for (int pr = warp; pr < 256; pr += 8) {
        int e = pr >> 4, f = pr & 15;
        int o = e * 128 + lane * 4;
        float4 mk = ((const float4*)(sMk + f * 128))[lane];
        float4 ga = *(const float4*)(gamma + o);
        float4 be = *(const float4*)(beta + o);
        float4 bb = *(const float4*)(b2 + o);
        float4 wA = *(const float4*)(w2 + (o + 0) * 4);
        float4 wB = *(const float4*)(w2 + (o + 1) * 4);
        float4 wC = *(const float4*)(w2 + (o + 2) * 4);
        float4 wD = *(const float4*)(w2 + (o + 3) * 4);
        float m0 = mk.x * ga.x, m1 = mk.y * ga.y, m2 = mk.z * ga.z, m3 = mk.w * ga.w;
        float t0 = m0 * wA.x + m1 * wB.x + m2 * wC.x + m3 * wD.x;
        float t1 = m0 * wA.y + m1 * wB.y + m2 * wC.y + m3 * wD.y;
        float t2 = m0 * wA.z + m1 * wB.z + m2 * wC.z + m3 * wD.z;
        float t3 = m0 * wA.w + m1 * wB.w + m2 * wC.w + m3 * wD.w;
        float tb = m0 * bb.x + m1 * bb.y + m2 * bb.z + m3 * bb.w;
        float gs = m0 + m1 + m2 + m3;
        float bs = mk.x * be.x + mk.y * be.y + mk.z * be.z + mk.w * be.w;
        t0 = wred(t0); t1 = wred(t1); t2 = wred(t2); t3 = wred(t3);
        tb = wred(tb); gs = wred(gs); bs = wred(bs);
        if (lane == 0) {
            int oo = e * TSTRIDE + f;
            stab[0 * TSIZE + oo] = t0;
            stab[1 * TSIZE + oo] = t1;
            stab[2 * TSIZE + oo] = t2;
            stab[3 * TSIZE + oo] = t3;
            stab[4 * TSIZE + oo] = tb;
            stab[5 * TSIZE + oo] = gs;
            stab[6 * TSIZE + oo] = bs;
        }
    }
    __syncthreads();

    // --- rank-4 moments: S1[4], Q[16], C[4], S0, SSB ---
    {
        float p[26];
        #pragma unroll
        for (int q = 0; q < 26; q++) p[q] = 0.f;
        int o0 = warp * 256 + lane * 8;
        #pragma unroll
        for (int k = 0; k < 8; k++) {
            int o = o0 + k;
            float4 w4 = *(const float4*)(w2 + o * 4);
            float b = b2[o];
            float w0v = w4.x, w1v = w4.y, w2v = w4.z, w3v = w4.w;
            p[0] += w0v; p[1] += w1v; p[2] += w2v; p[3] += w3v;
            p[4]  += w0v * w0v; p[5]  += w0v * w1v; p[6]  += w0v * w2v; p[7]  += w0v * w3v;
            p[8]  += w1v * w0v; p[9]  += w1v * w1v; p[10] += w1v * w2v; p[11] += w1v * w3v;
            p[12] += w2v * w0v; p[13] += w2v * w1v; p[14] += w2v * w2v; p[15] += w2v * w3v;
            p[16] += w3v * w0v; p[17] += w3v * w1v; p[18] += w3v * w2v; p[19] += w3v * w3v;
            p[20] += w0v * b; p[21] += w1v * b; p[22] += w2v * b; p[23] += w3v * b;
            p[24] += b; p[25] += b * b;
        }
        #pragma unroll
        for (int q = 0; q < 26; q++) p[q] = wred(p[q]);
        if (lane == 0) {
            #pragma unroll
            for (int q = 0; q < 26; q++) sred[warp * 26 + q] = p[q];
        }
        __syncthreads();
        if (tid < 26) {
            float s = 0.f;
            for (int w = 0; w < 8; w++) s += sred[w * 26 + tid];
            smisc[tid] = s;
        }
        __syncthreads();   // smisc write must land before sfin reuse is visible-safe
        if (tid < 4)  smisc[26 + tid] = b1[tid];
        if (tid < 16) smisc[30 + tid] = wv_b[tid];
        __syncthreads();
    }

    // ===================== stage 2: token stream =====================
    int start = (int)(((long long)blockIdx.x * NTOK) / GRID);
    int end   = (int)(((long long)(blockIdx.x + 1) * NTOK) / GRID);

    float* wsc  = sunion + warp * 1024;   // 2x2048B hidden buffers; aliased as reduce scratch
    uint32_t sb = (uint32_t)__cvta_generic_to_shared(wsc);
    float* part = wsc;                    // reduction scratch (720 <= 1024)
    float* sfw  = sfin + warp * 84;

    for (int t0 = start + warp * 4; t0 < end; t0 += 32) {
        const char* gp[4];
        #pragma unroll
        for (int i = 0; i < 4; i++) {
            int tt = t0 + i;
            if (tt > NTOK - 1) tt = NTOK - 1;
            gp[i] = (const char*)(hidden + (size_t)tt * 2048) + lane * 16;
        }

        // prologue: stage j=0
        #pragma unroll
        for (int i = 0; i < 4; i++) cpa16(sb + i * 512 + lane * 16, gp[i]);
        cpa_commit();

        unsigned long long acc[20][4];
        #pragma unroll
        for (int r = 0; r < 20; r++)
            #pragma unroll
            for (int i = 0; i < 4; i++) acc[r][i] = 0ull;

        #pragma unroll 1
        for (int j = 0; j < 16; j++) {
            if (j < 15) {
                #pragma unroll
                for (int i = 0; i < 4; i++)
                    cpa16(sb + ((j + 1) & 1) * 2048 + i * 512 + lane * 16,
                          gp[i] + (j + 1) * 512);
                cpa_commit();
                cpa_wait<1>();
            } else {
                cpa_wait<0>();
            }

            unsigned long long hvx[4], hvy[4];
            #pragma unroll
            for (int i = 0; i < 4; i++) {
                ulonglong2 h = *(const ulonglong2*)(wsc + (j & 1) * 512 + i * 128 + lane * 4);
                hvx[i] = h.x; hvy[i] = h.y;
            }
            const float* wj = sw + j * 128 + lane * 4;
            #pragma unroll
            for (int r = 0; r < 20; r++) {
                ulonglong2 wv = *(const ulonglong2*)(wj + r * 2048);
                #pragma unroll
                for (int i = 0; i < 4; i++) {
                    acc[r][i] = ffma2(hvx[i], wv.x, acc[r][i]);
                    acc[r][i] = ffma2(hvy[i], wv.y, acc[r][i]);
                }
            }
        }

        // --- chunked smem-transpose reduction: 4 chunks of 5 rows ---
        #pragma unroll
        for (int c = 0; c < 4; c++) {
            #pragma unroll
            for (int rl = 0; rl < 5; rl++) {
                #pragma unroll
                for (int i = 0; i < 4; i++) {
                    float2 f = upk(acc[c * 5 + rl][i]);
                    part[(rl * 4 + i) * 36 + lane] = f.x + f.y;
                }
            }
            __syncwarp();
            if (lane < 20) {
                const float4* p4 = (const float4*)(part + lane * 36);
                float4 q0 = p4[0], q1 = p4[1], q2 = p4[2], q3 = p4[3];
                float4 q4 = p4[4], q5 = p4[5], q6 = p4[6], q7 = p4[7];
                float s = ((q0.x + q0.y) + (q0.z + q0.w)) + ((q1.x + q1.y) + (q1.z + q1.w))
                        + ((q2.x + q2.y) + (q2.z + q2.w)) + ((q3.x + q3.y) + (q3.z + q3.w))
                        + ((q4.x + q4.y) + (q4.z + q4.w)) + ((q5.x + q5.y) + (q5.z + q5.w))
                        + ((q6.x + q6.y) + (q6.z + q6.w)) + ((q7.x + q7.y) + (q7.z + q7.w));
                sfw[(lane & 3) * 21 + c * 5 + (lane >> 2)] = s;
            }
            __syncwarp();
        }

        // --- epilogue: lanes (2e+h), h = half of f range ---
        int e  = lane >> 1;
        int fb = (lane & 1) << 3;
        const float* tb0 = stab + e * TSTRIDE + fb;

        #pragma unroll 1
        for (int i = 0; i < 4; i++) {
            if (t0 + i >= end) break;
            const float* sf = sfw + i * 21;
            float h0 = fmaxf(sf[16] + smisc[26], 0.f);
            float h1 = fmaxf(sf[17] + smisc[27], 0.f);
            float h2 = fmaxf(sf[18] + smisc[28], 0.f);
            float h3 = fmaxf(sf[19] + smisc[29], 0.f);
            float mu = (h0 * smisc[0] + h1 * smisc[1] + h2 * smisc[2] + h3 * smisc[3]
                        + smisc[24]) * (1.f / 2048.f);
            const float* Q = smisc + 4;
            float ex = smisc[25]
                     + 2.f * (h0 * smisc[20] + h1 * smisc[21] + h2 * smisc[22] + h3 * smisc[23])
                     + h0 * (h0 * Q[0]  + h1 * Q[1]  + h2 * Q[2]  + h3 * Q[3])
                     + h1 * (h0 * Q[4]  + h1 * Q[5]  + h2 * Q[6]  + h3 * Q[7])
                     + h2 * (h0 * Q[8]  + h1 * Q[9]  + h2 * Q[10] + h3 * Q[11])
                     + h3 * (h0 * Q[12] + h1 * Q[13] + h2 * Q[14] + h3 * Q[15]);
            ex *= (1.f / 2048.f);
            float rstd = rsqrtf(ex - mu * mu + 1e-5f);

            float Lv[8];
            float Lmax = -1e30f;
            #pragma unroll
            for (int ff = 0; ff < 8; ff++) {
                float a = tb0[4 * TSIZE + ff];                 // Tb
                a = fmaf(h0, tb0[0 * TSIZE + ff], a);
                a = fmaf(h1, tb0[1 * TSIZE + ff], a);
                a = fmaf(h2, tb0[2 * TSIZE + ff], a);
                a = fmaf(h3, tb0[3 * TSIZE + ff], a);
                a = fmaf(-mu, tb0[5 * TSIZE + ff], a);         // Gs
                float L = fmaf(rstd, a, tb0[6 * TSIZE + ff]);  // Bs
                Lv[ff] = L;
                Lmax = fmaxf(Lmax, L);
            }
            Lmax = fmaxf(Lmax, __shfl_xor_sync(~0u, Lmax, 1));
            float se = 0.f, gd = 0.f;
            #pragma unroll
            for (int ff = 0; ff < 8; ff++) {
                float p = __expf(Lv[ff] - Lmax);
                se += p;
                gd = fmaf(p, sf[fb + ff] + smisc[30 + fb + ff], gd);
            }
            se += __shfl_xor_sync(~0u, se, 1);
            gd += __shfl_xor_sync(~0u, gd, 1);
            float gate = gd / se;

            // rw = softmax over e (parity-preserving butterfly)
            float gmax = gate;
            #pragma unroll
            for (int m = 2; m <= 16; m <<= 1)
                gmax = fmaxf(gmax, __shfl_xor_sync(~0u, gmax, m));
            float er = __expf(gate - gmax);
            float es = er;
            #pragma unroll
            for (int m = 2; m <= 16; m <<= 1)
                es += __shfl_xor_sync(~0u, es, m);
            float rw = er / es;

            // top-2 over e with index tie-break (lower index wins)
            float v1 = rw, v2 = -1.f;
            int i1 = e, i2 = 16;
            #pragma unroll
            for (int m = 2; m <= 16; m <<= 1) {
                float ov1 = __shfl_xor_sync(~0u, v1, m);
                int   oi1 = __shfl_xor_sync(~0u, i1, m);
                float ov2 = __shfl_xor_sync(~0u, v2, m);
                int   oi2 = __shfl_xor_sync(~0u, i2, m);
                bool fw = (v1 > ov1) || (v1 == ov1 && i1 < oi1);
                float w1v = fw ? v1 : ov1;  int w1i = fw ? i1 : oi1;
                float l1v = fw ? ov1 : v1;  int l1i = fw ? oi1 : i1;
                float c2v = fw ? v2 : ov2;  int c2i = fw ? i2 : oi2;
                bool sv = (l1v > c2v) || (l1v == c2v && l1i < c2i);
                v1 = w1v; i1 = w1i;
                v2 = sv ? l1v : c2v;
                i2 = sv ? l1i : c2i;
            }

            float texp = __expf((v2 - v1) * 10.f);
            float inv = 1.f / (1.f + texp);
            float ov = (e == i1) ? inv : ((e == i2) ? texp * inv : 0.f);
            if (!(lane & 1)) out[(size_t)(t0 + i) * 16 + e] = ov;
        }
    }
}

// ---------------------------------------------------------------------------
extern "C" void kernel_launch(void* const* d_in, const int* in_sizes, int n_in,
                              void* d_out, int out_size)
{
    const float* hidden = (const float*)d_in[0];
    const float* ee     = (const float*)d_in[1];
    const float* gamma  = (const float*)d_in[2];
    const float* beta   = (const float*)d_in[3];
    const float* wv_w   = (const float*)d_in[4];
    const float* wv_b   = (const float*)d_in[5];
    const float* w1     = (const float*)d_in[6];
    const float* b1     = (const float*)d_in[7];
    const float* w2     = (const float*)d_in[8];
    const float* b2     = (const float*)d_in[9];
    const float* wq     = (const float*)d_in[10];
    const float* wk     = (const float*)d_in[11];
    float* out = (float*)d_out;

    cudaFuncSetAttribute(fused_kernel, cudaFuncAttributeMaxDynamicSharedMemorySize,
                         SMEM_BYTES);

    fused_kernel<<<GRID, TPB, SMEM_BYTES>>>(hidden, ee, gamma, beta, wv_w, wv_b,
                                            w1, b1, w2, b2, wq, wk, out);
}

// round 6
// speedup vs baseline: 1.7099x; 1.0249x over previous
#include <cuda_runtime.h>
#include <cstdint>
#include <math.h>

// ---------------------------------------------------------------------------
// Hybrid router. B*S=16384 tokens, IN=2048, E=16, D=128, A=128, R=4, top_k=2.
// Single fused kernel, TPB=384 (12 warps = 6 pairs). Each pair processes 4
// tokens; within a pair, warp sub=0 computes rows 0..9 and sub=1 rows 10..19
// (16 Wv rows + 4 mlp_w1 rows total), each as length-2048 dots vs hidden with
// packed fp32x2 FMA. Hidden comes via direct LDG with 1-iter register
// prefetch (pair partner hits L2). Tiny per-token epilogue (two softmaxes,
// attention fold, rank-4 LN moments, top-2 sharpened softmax).
// ---------------------------------------------------------------------------

#define NTOK 16384
#define GRID 148
#define TPB  384

#define TSTRIDE 35
#define TSIZE   544

// smem layout (floats)
#define SW_F      40960            // 20 rows x 2048 weights (16 Wv + 4 w1)
#define STAB_F    (7 * TSIZE)      // 3808
#define SMISC_F   64
#define SFIN_F    (6 * 84)         // per-pair final sums: 4 tok x 21
#define SPART_F   (12 * 736)       // per-warp reduce scratch (also prep scratch)
#define OFF_STAB  SW_F
#define OFF_SMISC (OFF_STAB + STAB_F)
#define OFF_SFIN  (OFF_SMISC + SMISC_F)
#define OFF_SPART (OFF_SFIN + SFIN_F)
#define SMEM_FLOATS (OFF_SPART + SPART_F)
#define SMEM_BYTES  (SMEM_FLOATS * 4)

// ---------------------------------------------------------------------------
__device__ __forceinline__ unsigned long long ffma2(unsigned long long a,
                                                    unsigned long long b,
                                                    unsigned long long c) {
    unsigned long long d;
    asm("fma.rn.f32x2 %0, %1, %2, %3;" : "=l"(d) : "l"(a), "l"(b), "l"(c));
    return d;
}
__device__ __forceinline__ float2 upk(unsigned long long v) {
    float2 f;
    asm("mov.b64 {%0, %1}, %2;" : "=f"(f.x), "=f"(f.y) : "l"(v));
    return f;
}
__device__ __forceinline__ float wred(float v) {
    #pragma unroll
    for (int m = 16; m; m >>= 1) v += __shfl_xor_sync(~0u, v, m);
    return v;
}
__device__ __forceinline__ void pair_bar(int pair) {
    asm volatile("bar.sync %0, 64;" :: "r"(pair + 1) : "memory");
}

// ---------------------------------------------------------------------------
__global__ void __launch_bounds__(TPB, 1)
fused_kernel(const float* __restrict__ hidden, const float* __restrict__ ee,
             const float* __restrict__ gamma, const float* __restrict__ beta,
             const float* __restrict__ wv_w, const float* __restrict__ wv_b,
             const float* __restrict__ w1, const float* __restrict__ b1,
             const float* __restrict__ w2, const float* __restrict__ b2,
             const float* __restrict__ wq, const float* __restrict__ wk,
             float* __restrict__ out)
{
    extern __shared__ float smem[];
    float* sw    = smem;
    float* stab  = smem + OFF_STAB;
    float* smisc = smem + OFF_SMISC;
    float* sfin  = smem + OFF_SFIN;
    float* spart = smem + OFF_SPART;

    int tid = threadIdx.x, lane = tid & 31, warp = tid >> 5;
    int pair = warp >> 1, sub = warp & 1;

    // ===================== stage 0: weights -> smem =====================
    for (int idx = tid; idx < 8192; idx += TPB)
        ((float4*)sw)[idx] = ((const float4*)wv_w)[idx];
    for (int idx = tid; idx < 2048; idx += TPB)
        ((float4*)sw)[8192 + idx] = ((const float4*)w1)[idx];

    // ===================== stage 1: per-block precompute =====================
    float* sge  = spart;           // 2048
    float* sk_  = spart + 2048;    // 2048
    float* sMk  = spart + 4096;    // 2048
    float* sred = sfin;            // scratch (re-used later as per-pair sums)

    // --- LN of expert_embedding over all 2048 ---
    {
        float ls = 0.f, lq = 0.f;
        for (int i = tid; i < 2048; i += TPB) {
            float v = ee[i];
            sge[i] = v; ls += v; lq += v * v;
        }
        ls = wred(ls); lq = wred(lq);
        if (lane == 0) { sred[warp] = ls; sred[16 + warp] = lq; }
        __syncthreads();
        if (tid == 0) {
            float s = 0.f, q = 0.f;
            for (int i = 0; i < 12; i++) { s += sred[i]; q += sred[16 + i]; }
            float mu = s * (1.0f / 2048.0f);
            float var = q * (1.0f / 2048.0f) - mu * mu;
            sred[32] = mu; sred[33] = rsqrtf(var + 1e-5f);
        }
        __syncthreads();
        float mu = sred[32], rs = sred[33];
        for (int i = tid; i < 2048; i += TPB)
            sge[i] = (sge[i] - mu) * rs * gamma[i] + beta[i];
        __syncthreads();
    }

    // --- k[f][a] = sum_d ge[f,d] * Wk[a,d] (one warp per output) ---
    for (int o = warp; o < 2048; o += 12) {
        int f = o >> 7, a = o & 127;
        float4 g = ((const float4*)(sge + f * 128))[lane];
        float4 w = ((const float4*)(wk + a * 128))[lane];
        float p = fmaf(g.x, w.x, fmaf(g.y, w.y, fmaf(g.z, w.z, g.w * w.w)));
        p = wred(p);
        if (lane == 0) sk_[f * 128 + a] = p;
    }
    __syncthreads();

    // --- Mk[f][d] = scale * sum_a k[f,a]*Wq[a,d] (lane covers d, coalesced) ---
    for (int task = warp; task < 64; task += 12) {
        int f = task >> 2, d = (task & 3) * 32 + lane;
        const float* kf = sk_ + f * 128;
        float a0 = 0.f, a1 = 0.f;
        #pragma unroll 8
        for (int a = 0; a < 128; a += 2) {
            a0 = fmaf(kf[a],     wq[a * 128 + d],       a0);
            a1 = fmaf(kf[a + 1], wq[(a + 1) * 128 + d], a1);
        }
        sMk[f * 128 + d] = (a0 + a1) * 0.08838834764831845f;  // 1/sqrt(128)
    }
    __syncthreads();

    // --- tables T0..T3, Tb, Gs, Bs per (e,f): one warp per pair ---
    for (int pr = warp; pr < 256; pr += 12) {
        int e = pr >> 4, f = pr & 15;
        int o = e * 128 + lane * 4;
        float4 mk = ((const float4*)(sMk + f * 128))[lane];
        float4 ga = *(const float4*)(gamma + o);
        float4 be = *(const float4*)(beta + o);
        float4 bb = *(const float4*)(b2 + o);
        float4 wA = *(const float4*)(w2 + (o + 0) * 4);
        float4 wB = *(const float4*)(w2 + (o + 1) * 4);
        float4 wC = *(const float4*)(w2 + (o + 2) * 4);
        float4 wD = *(const float4*)(w2 + (o + 3) * 4);
        float m0 = mk.x * ga.x, m1 = mk.y * ga.y, m2 = mk.z * ga.z, m3 = mk.w * ga.w;
        float t0 = m0 * wA.x + m1 * wB.x + m2 * wC.x + m3 * wD.x;
        float t1 = m0 * wA.y + m1 * wB.y + m2 * wC.y + m3 * wD.y;
        float t2 = m0 * wA.z + m1 * wB.z + m2 * wC.z + m3 * wD.z;
        float t3 = m0 * wA.w + m1 * wB.w + m2 * wC.w + m3 * wD.w;
        float tb = m0 * bb.x + m1 * bb.y + m2 * bb.z + m3 * bb.w;
        float gs = m0 + m1 + m2 + m3;
        float bs = mk.x * be.x + mk.y * be.y + mk.z * be.z + mk.w * be.w;
        t0 = wred(t0); t1 = wred(t1); t2 = wred(t2); t3 = wred(t3);
        tb = wred(tb); gs = wred(gs); bs = wred(bs);
        if (lane == 0) {
            int oo = e * TSTRIDE + f;
            stab[0 * TSIZE + oo] = t0;
            stab[1 * TSIZE + oo] = t1;
            stab[2 * TSIZE + oo] = t2;
            stab[3 * TSIZE + oo] = t3;
            stab[4 * TSIZE + oo] = tb;
            stab[5 * TSIZE + oo] = gs;
            stab[6 * TSIZE + oo] = bs;
        }
    }
    __syncthreads();

    // --- rank-4 moments of dyn: S1[4], Q[16], C[4], S0, SSB ---
    {
        float p[26];
        #pragma unroll
        for (int q = 0; q < 26; q++) p[q] = 0.f;
        for (int o = tid; o < 2048; o += TPB) {
            float4 w4 = *(const float4*)(w2 + o * 4);
            float b = b2[o];
            float w0v = w4.x, w1v = w4.y, w2v = w4.z, w3v = w4.w;
            p[0] += w0v; p[1] += w1v; p[2] += w2v; p[3] += w3v;
            p[4]  += w0v * w0v; p[5]  += w0v * w1v; p[6]  += w0v * w2v; p[7]  += w0v * w3v;
            p[8]  += w1v * w0v; p[9]  += w1v * w1v; p[10] += w1v * w2v; p[11] += w1v * w3v;
            p[12] += w2v * w0v; p[13] += w2v * w1v; p[14] += w2v * w2v; p[15] += w2v * w3v;
            p[16] += w3v * w0v; p[17] += w3v * w1v; p[18] += w3v * w2v; p[19] += w3v * w3v;
            p[20] += w0v * b; p[21] += w1v * b; p[22] += w2v * b; p[23] += w3v * b;
            p[24] += b; p[25] += b * b;
        }
        #pragma unroll
        for (int q = 0; q < 26; q++) p[q] = wred(p[q]);
        if (lane == 0) {
            #pragma unroll
            for (int q = 0; q < 26; q++) sred[warp * 26 + q] = p[q];
        }
        __syncthreads();
        if (tid < 26) {
            float s = 0.f;
            for (int w = 0; w < 12; w++) s += sred[w * 26 + tid];
            smisc[tid] = s;
        }
        __syncthreads();
        if (tid < 4)  smisc[26 + tid] = b1[tid];
        if (tid < 16) smisc[30 + tid] = wv_b[tid];
        __syncthreads();
    }

    // ===================== stage 2: token stream =====================
    int start = (int)(((long long)blockIdx.x * NTOK) / GRID);
    int end   = (int)(((long long)(blockIdx.x + 1) * NTOK) / GRID);

    float* part = spart + warp * 736;     // per-warp transpose scratch (720 used)
    float* sfw  = sfin + pair * 84;       // per-pair sums: [4 tok][21]
    const float* swr = sw + sub * 10 * 2048;  // this warp's 10 rows

    for (int t0 = start + pair * 4; t0 < end; t0 += 24) {
        const char* gp[4];
        #pragma unroll
        for (int i = 0; i < 4; i++) {
            int tt = t0 + i;
            if (tt > NTOK - 1) tt = NTOK - 1;
            gp[i] = (const char*)(hidden + (size_t)tt * 2048) + lane * 16;
        }

        unsigned long long acc[10][4];
        #pragma unroll
        for (int r = 0; r < 10; r++)
            #pragma unroll
            for (int i = 0; i < 4; i++) acc[r][i] = 0ull;

        ulonglong2 nhv[4];
        #pragma unroll
        for (int i = 0; i < 4; i++) nhv[i] = *(const ulonglong2*)gp[i];

        #pragma unroll 1
        for (int j = 0; j < 16; j++) {
            unsigned long long hvx[4], hvy[4];
            #pragma unroll
            for (int i = 0; i < 4; i++) { hvx[i] = nhv[i].x; hvy[i] = nhv[i].y; }
            if (j < 15) {
                #pragma unroll
                for (int i = 0; i < 4; i++)
                    nhv[i] = *(const ulonglong2*)(gp[i] + (j + 1) * 512);
            }
            const float* wj = swr + j * 128 + lane * 4;
            #pragma unroll
            for (int r = 0; r < 10; r++) {
                ulonglong2 wv = *(const ulonglong2*)(wj + r * 2048);
                #pragma unroll
                for (int i = 0; i < 4; i++) {
                    acc[r][i] = ffma2(hvx[i], wv.x, acc[r][i]);
                    acc[r][i] = ffma2(hvy[i], wv.y, acc[r][i]);
                }
            }
        }

        // --- chunked smem-transpose reduction: 2 chunks of 5 rows ---
        #pragma unroll
        for (int c = 0; c < 2; c++) {
            #pragma unroll
            for (int rl = 0; rl < 5; rl++) {
                #pragma unroll
                for (int i = 0; i < 4; i++) {
                    float2 f = upk(acc[c * 5 + rl][i]);
                    part[(rl * 4 + i) * 36 + lane] = f.x + f.y;
                }
            }
            __syncwarp();
            if (lane < 20) {
                const float4* p4 = (const float4*)(part + lane * 36);
                float4 q0 = p4[0], q1 = p4[1], q2 = p4[2], q3 = p4[3];
                float4 q4 = p4[4], q5 = p4[5], q6 = p4[6], q7 = p4[7];
                float s = ((q0.x + q0.y) + (q0.z + q0.w)) + ((q1.x + q1.y) + (q1.z + q1.w))
                        + ((q2.x + q2.y) + (q2.z + q2.w)) + ((q3.x + q3.y) + (q3.z + q3.w))
                        + ((q4.x + q4.y) + (q4.z + q4.w)) + ((q5.x + q5.y) + (q5.z + q5.w))
                        + ((q6.x + q6.y) + (q6.z + q6.w)) + ((q7.x + q7.y) + (q7.z + q7.w));
                sfw[(lane & 3) * 21 + sub * 10 + c * 5 + (lane >> 2)] = s;
            }
            __syncwarp();
        }

        pair_bar(pair);   // pair's 20 sums visible to both warps

        // --- epilogue: this warp handles tokens {sub*2, sub*2+1} ---
        int e  = lane >> 1;
        int fb = (lane & 1) << 3;
        const float* tb0 = stab + e * TSTRIDE + fb;

        #pragma unroll 1
        for (int i = sub * 2; i < sub * 2 + 2; i++) {
            if (t0 + i >= end) break;
            const float* sf = sfw + i * 21;
            float h0 = fmaxf(sf[16] + smisc[26], 0.f);
            float h1 = fmaxf(sf[17] + smisc[27], 0.f);
            float h2 = fmaxf(sf[18] + smisc[28], 0.f);
            float h3 = fmaxf(sf[19] + smisc[29], 0.f);
            float mu = (h0 * smisc[0] + h1 * smisc[1] + h2 * smisc[2] + h3 * smisc[3]
                        + smisc[24]) * (1.f / 2048.f);
            const float* Q = smisc + 4;
            float ex = smisc[25]
                     + 2.f * (h0 * smisc[20] + h1 * smisc[21] + h2 * smisc[22] + h3 * smisc[23])
                     + h0 * (h0 * Q[0]  + h1 * Q[1]  + h2 * Q[2]  + h3 * Q[3])
                     + h1 * (h0 * Q[4]  + h1 * Q[5]  + h2 * Q[6]  + h3 * Q[7])
                     + h2 * (h0 * Q[8]  + h1 * Q[9]  + h2 * Q[10] + h3 * Q[11])
                     + h3 * (h0 * Q[12] + h1 * Q[13] + h2 * Q[14] + h3 * Q[15]);
            ex *= (1.f / 2048.f);
            float rstd = rsqrtf(ex - mu * mu + 1e-5f);

            float Lv[8];
            float Lmax = -1e30f;
            #pragma unroll
            for (int ff = 0; ff < 8; ff++) {
                float a = tb0[4 * TSIZE + ff];                 // Tb
                a = fmaf(h0, tb0[0 * TSIZE + ff], a);
                a = fmaf(h1, tb0[1 * TSIZE + ff], a);
                a = fmaf(h2, tb0[2 * TSIZE + ff], a);
                a = fmaf(h3, tb0[3 * TSIZE + ff], a);
                a = fmaf(-mu, tb0[5 * TSIZE + ff], a);         // Gs
                float L = fmaf(rstd, a, tb0[6 * TSIZE + ff]);  // Bs
                Lv[ff] = L;
                Lmax = fmaxf(Lmax, L);
            }
            Lmax = fmaxf(Lmax, __shfl_xor_sync(~0u, Lmax, 1));
            float se = 0.f, gd = 0.f;
            #pragma unroll
            for (int ff = 0; ff < 8; ff++) {
                float p = __expf(Lv[ff] - Lmax);
                se += p;
                gd = fmaf(p, sf[fb + ff] + smisc[30 + fb + ff], gd);
            }
            se += __shfl_xor_sync(~0u, se, 1);
            gd += __shfl_xor_sync(~0u, gd, 1);
            float gate = gd / se;

            // rw = softmax over e (parity-preserving butterfly)
            float gmax = gate;
            #pragma unroll
            for (int m = 2; m <= 16; m <<= 1)
                gmax = fmaxf(gmax, __shfl_xor_sync(~0u, gmax, m));
            float er = __expf(gate - gmax);
            float es = er;
            #pragma unroll
            for (int m = 2; m <= 16; m <<= 1)
                es += __shfl_xor_sync(~0u, es, m);
            float rw = er / es;

            // top-2 over e with index tie-break (lower index wins)
            float v1 = rw, v2 = -1.f;
            int i1 = e, i2 = 16;
            #pragma unroll
            for (int m = 2; m <= 16; m <<= 1) {
                float ov1 = __shfl_xor_sync(~0u, v1, m);
                int   oi1 = __shfl_xor_sync(~0u, i1, m);
                float ov2 = __shfl_xor_sync(~0u, v2, m);
                int   oi2 = __shfl_xor_sync(~0u, i2, m);
                bool fw = (v1 > ov1) || (v1 == ov1 && i1 < oi1);
                float w1v = fw ? v1 : ov1;  int w1i = fw ? i1 : oi1;
                float l1v = fw ? ov1 : v1;  int l1i = fw ? oi1 : i1;
                float c2v = fw ? v2 : ov2;  int c2i = fw ? i2 : oi2;
                bool sv = (l1v > c2v) || (l1v == c2v && l1i < c2i);
                v1 = w1v; i1 = w1i;
                v2 = sv ? l1v : c2v;
                i2 = sv ? l1i : c2i;
            }

            float texp = __expf((v2 - v1) * 10.f);
            float inv = 1.f / (1.f + texp);
            float ov = (e == i1) ? inv : ((e == i2) ? texp * inv : 0.f);
            if (!(lane & 1)) out[(size_t)(t0 + i) * 16 + e] = ov;
        }

        pair_bar(pair);   // sums consumed; safe to overwrite next iteration
    }
}

// ---------------------------------------------------------------------------
extern "C" void kernel_launch(void* const* d_in, const int* in_sizes, int n_in,
                              void* d_out, int out_size)
{
    const float* hidden = (const float*)d_in[0];
    const float* ee     = (const float*)d_in[1];
    const float* gamma  = (const float*)d_in[2];
    const float* beta   = (const float*)d_in[3];
    const float* wv_w   = (const float*)d_in[4];
    const float* wv_b   = (const float*)d_in[5];
    const float* w1     = (const float*)d_in[6];
    const float* b1     = (const float*)d_in[7];
    const float* w2     = (const float*)d_in[8];
    const float* b2     = (const float*)d_in[9];
    const float* wq     = (const float*)d_in[10];
    const float* wk     = (const float*)d_in[11];
    float* out = (float*)d_out;

    cudaFuncSetAttribute(fused_kernel, cudaFuncAttributeMaxDynamicSharedMemorySize,
                         SMEM_BYTES);

    fused_kernel<<<GRID, TPB, SMEM_BYTES>>>(hidden, ee, gamma, beta, wv_w, wv_b,
                                            w1, b1, w2, b2, wq, wk, out);
}

// round 7
// speedup vs baseline: 1.9540x; 1.1428x over previous
#include <cuda_runtime.h>
#include <cstdint>
#include <math.h>

// ---------------------------------------------------------------------------
// Hybrid router. B*S=16384 tokens, IN=2048, E=16, D=128, A=128, R=4, top_k=2.
// Single fused kernel, TPB=512 (16 warps = 8 pairs). Each pair processes 4
// tokens; warp sub=0 computes rows 0..9, sub=1 rows 10..19 (16 Wv + 4 w1),
// each a length-2048 dot vs hidden, plain fp32 FMA (no packed asm). Hidden
// via direct LDG with 1-iter register prefetch. Tiny per-token epilogue.
// ---------------------------------------------------------------------------

#define NTOK 16384
#define GRID 148
#define TPB  512
#define NWARP 16
#define NPAIR 8

#define TSTRIDE 35
#define TSIZE   544

// smem layout (floats)
#define SW_F      40960            // 20 rows x 2048 weights (16 Wv + 4 w1)
#define STAB_F    (7 * TSIZE)      // 3808
#define SMISC_F   64
#define SFIN_F    (NPAIR * 84)     // per-pair final sums: 4 tok x 21
#define SPART_F   (NWARP * 736)    // per-warp reduce scratch (also prep scratch)
#define OFF_STAB  SW_F
#define OFF_SMISC (OFF_STAB + STAB_F)
#define OFF_SFIN  (OFF_SMISC + SMISC_F)
#define OFF_SPART (OFF_SFIN + SFIN_F)
#define SMEM_FLOATS (OFF_SPART + SPART_F)
#define SMEM_BYTES  (SMEM_FLOATS * 4)

// ---------------------------------------------------------------------------
__device__ __forceinline__ float wred(float v) {
    #pragma unroll
    for (int m = 16; m; m >>= 1) v += __shfl_xor_sync(~0u, v, m);
    return v;
}
__device__ __forceinline__ void pair_bar(int pair) {
    asm volatile("bar.sync %0, 64;" :: "r"(pair + 1) : "memory");
}

// ---------------------------------------------------------------------------
__global__ void __launch_bounds__(TPB, 1)
fused_kernel(const float* __restrict__ hidden, const float* __restrict__ ee,
             const float* __restrict__ gamma, const float* __restrict__ beta,
             const float* __restrict__ wv_w, const float* __restrict__ wv_b,
             const float* __restrict__ w1, const float* __restrict__ b1,
             const float* __restrict__ w2, const float* __restrict__ b2,
             const float* __restrict__ wq, const float* __restrict__ wk,
             float* __restrict__ out)
{
    extern __shared__ float smem[];
    float* sw    = smem;
    float* stab  = smem + OFF_STAB;
    float* smisc = smem + OFF_SMISC;
    float* sfin  = smem + OFF_SFIN;
    float* spart = smem + OFF_SPART;

    int tid = threadIdx.x, lane = tid & 31, warp = tid >> 5;
    int pair = warp >> 1, sub = warp & 1;

    // ===================== stage 0: weights -> smem =====================
    for (int idx = tid; idx < 8192; idx += TPB)
        ((float4*)sw)[idx] = ((const float4*)wv_w)[idx];
    for (int idx = tid; idx < 2048; idx += TPB)
        ((float4*)sw)[8192 + idx] = ((const float4*)w1)[idx];

    // ===================== stage 1: per-block precompute =====================
    float* sge  = spart;           // 2048
    float* sk_  = spart + 2048;    // 2048
    float* sMk  = spart + 4096;    // 2048
    float* sred = sfin;            // scratch (re-used later as per-pair sums)

    // --- LN of expert_embedding over all 2048 ---
    {
        float ls = 0.f, lq = 0.f;
        for (int i = tid; i < 2048; i += TPB) {
            float v = ee[i];
            sge[i] = v; ls += v; lq += v * v;
        }
        ls = wred(ls); lq = wred(lq);
        if (lane == 0) { sred[warp] = ls; sred[16 + warp] = lq; }
        __syncthreads();
        if (tid == 0) {
            float s = 0.f, q = 0.f;
            for (int i = 0; i < NWARP; i++) { s += sred[i]; q += sred[16 + i]; }
            float mu = s * (1.0f / 2048.0f);
            float var = q * (1.0f / 2048.0f) - mu * mu;
            sred[32] = mu; sred[33] = rsqrtf(var + 1e-5f);
        }
        __syncthreads();
        float mu = sred[32], rs = sred[33];
        for (int i = tid; i < 2048; i += TPB)
            sge[i] = (sge[i] - mu) * rs * gamma[i] + beta[i];
        __syncthreads();
    }

    // --- k[f][a] = sum_d ge[f,d] * Wk[a,d] (one warp per output) ---
    for (int o = warp; o < 2048; o += NWARP) {
        int f = o >> 7, a = o & 127;
        float4 g = ((const float4*)(sge + f * 128))[lane];
        float4 w = ((const float4*)(wk + a * 128))[lane];
        float p = fmaf(g.x, w.x, fmaf(g.y, w.y, fmaf(g.z, w.z, g.w * w.w)));
        p = wred(p);
        if (lane == 0) sk_[f * 128 + a] = p;
    }
    __syncthreads();

    // --- Mk[f][d] = scale * sum_a k[f,a]*Wq[a,d] (lane covers d, coalesced) ---
    for (int task = warp; task < 64; task += NWARP) {
        int f = task >> 2, d = (task & 3) * 32 + lane;
        const float* kf = sk_ + f * 128;
        float a0 = 0.f, a1 = 0.f;
        #pragma unroll 8
        for (int a = 0; a < 128; a += 2) {
            a0 = fmaf(kf[a],     wq[a * 128 + d],       a0);
            a1 = fmaf(kf[a + 1], wq[(a + 1) * 128 + d], a1);
        }
        sMk[f * 128 + d] = (a0 + a1) * 0.08838834764831845f;  // 1/sqrt(128)
    }
    __syncthreads();

    // --- tables T0..T3, Tb, Gs, Bs per (e,f): one warp per pair ---
    for (int pr = warp; pr < 256; pr += NWARP) {
        int e = pr >> 4, f = pr & 15;
        int o = e * 128 + lane * 4;
        float4 mk = ((const float4*)(sMk + f * 128))[lane];
        float4 ga = *(const float4*)(gamma + o);
        float4 be = *(const float4*)(beta + o);
        float4 bb = *(const float4*)(b2 + o);
        float4 wA = *(const float4*)(w2 + (o + 0) * 4);
        float4 wB = *(const float4*)(w2 + (o + 1) * 4);
        float4 wC = *(const float4*)(w2 + (o + 2) * 4);
        float4 wD = *(const float4*)(w2 + (o + 3) * 4);
        float m0 = mk.x * ga.x, m1 = mk.y * ga.y, m2 = mk.z * ga.z, m3 = mk.w * ga.w;
        float t0 = m0 * wA.x + m1 * wB.x + m2 * wC.x + m3 * wD.x;
        float t1 = m0 * wA.y + m1 * wB.y + m2 * wC.y + m3 * wD.y;
        float t2 = m0 * wA.z + m1 * wB.z + m2 * wC.z + m3 * wD.z;
        float t3 = m0 * wA.w + m1 * wB.w + m2 * wC.w + m3 * wD.w;
        float tb = m0 * bb.x + m1 * bb.y + m2 * bb.z + m3 * bb.w;
        float gs = m0 + m1 + m2 + m3;
        float bs = mk.x * be.x + mk.y * be.y + mk.z * be.z + mk.w * be.w;
        t0 = wred(t0); t1 = wred(t1); t2 = wred(t2); t3 = wred(t3);
        tb = wred(tb); gs = wred(gs); bs = wred(bs);
        if (lane == 0) {
            int oo = e * TSTRIDE + f;
            stab[0 * TSIZE + oo] = t0;
            stab[1 * TSIZE + oo] = t1;
            stab[2 * TSIZE + oo] = t2;
            stab[3 * TSIZE + oo] = t3;
            stab[4 * TSIZE + oo] = tb;
            stab[5 * TSIZE + oo] = gs;
            stab[6 * TSIZE + oo] = bs;
        }
    }
    __syncthreads();

    // --- rank-4 moments of dyn: S1[4], Q[16], C[4], S0, SSB ---
    {
        float p[26];
        #pragma unroll
        for (int q = 0; q < 26; q++) p[q] = 0.f;
        for (int o = tid; o < 2048; o += TPB) {
            float4 w4 = *(const float4*)(w2 + o * 4);
            float b = b2[o];
            float w0v = w4.x, w1v = w4.y, w2v = w4.z, w3v = w4.w;
            p[0] += w0v; p[1] += w1v; p[2] += w2v; p[3] += w3v;
            p[4]  += w0v * w0v; p[5]  += w0v * w1v; p[6]  += w0v * w2v; p[7]  += w0v * w3v;
            p[8]  += w1v * w0v; p[9]  += w1v * w1v; p[10] += w1v * w2v; p[11] += w1v * w3v;
            p[12] += w2v * w0v; p[13] += w2v * w1v; p[14] += w2v * w2v; p[15] += w2v * w3v;
            p[16] += w3v * w0v; p[17] += w3v * w1v; p[18] += w3v * w2v; p[19] += w3v * w3v;
            p[20] += w0v * b; p[21] += w1v * b; p[22] += w2v * b; p[23] += w3v * b;
            p[24] += b; p[25] += b * b;
        }
        #pragma unroll
        for (int q = 0; q < 26; q++) p[q] = wred(p[q]);
        if (lane == 0) {
            #pragma unroll
            for (int q = 0; q < 26; q++) sred[warp * 26 + q] = p[q];
        }
        __syncthreads();
        if (tid < 26) {
            float s = 0.f;
            for (int w = 0; w < NWARP; w++) s += sred[w * 26 + tid];
            smisc[tid] = s;
        }
        __syncthreads();
        if (tid < 4)  smisc[26 + tid] = b1[tid];
        if (tid < 16) smisc[30 + tid] = wv_b[tid];
        __syncthreads();
    }

    // ===================== stage 2: token stream =====================
    int start = (int)(((long long)blockIdx.x * NTOK) / GRID);
    int end   = (int)(((long long)(blockIdx.x + 1) * NTOK) / GRID);

    float* part = spart + warp * 736;     // per-warp transpose scratch (720 used)
    float* sfw  = sfin + pair * 84;       // per-pair sums: [4 tok][21]
    const float* swr = sw + sub * 10 * 2048;  // this warp's 10 rows

    for (int t0 = start + pair * 4; t0 < end; t0 += NPAIR * 4) {
        const char* gp[4];
        #pragma unroll
        for (int i = 0; i < 4; i++) {
            int tt = t0 + i;
            if (tt > NTOK - 1) tt = NTOK - 1;
            gp[i] = (const char*)(hidden + (size_t)tt * 2048) + lane * 16;
        }

        float acc[10][4];
        #pragma unroll
        for (int r = 0; r < 10; r++)
            #pragma unroll
            for (int i = 0; i < 4; i++) acc[r][i] = 0.f;

        float4 nhv[4];
        #pragma unroll
        for (int i = 0; i < 4; i++) nhv[i] = *(const float4*)gp[i];

        #pragma unroll 1
        for (int j = 0; j < 16; j++) {
            float4 hv[4];
            #pragma unroll
            for (int i = 0; i < 4; i++) hv[i] = nhv[i];
            if (j < 15) {
                #pragma unroll
                for (int i = 0; i < 4; i++)
                    nhv[i] = *(const float4*)(gp[i] + (j + 1) * 512);
            }
            const float4* wj = (const float4*)(swr + j * 128) + lane;
            #pragma unroll
            for (int r = 0; r < 10; r++) {
                float4 wv = wj[r * 512];
                #pragma unroll
                for (int i = 0; i < 4; i++) {
                    acc[r][i] = fmaf(hv[i].x, wv.x, acc[r][i]);
                    acc[r][i] = fmaf(hv[i].y, wv.y, acc[r][i]);
                    acc[r][i] = fmaf(hv[i].z, wv.z, acc[r][i]);
                    acc[r][i] = fmaf(hv[i].w, wv.w, acc[r][i]);
                }
            }
        }

        // --- chunked smem-transpose reduction: 2 chunks of 5 rows ---
        #pragma unroll
        for (int c = 0; c < 2; c++) {
            #pragma unroll
            for (int rl = 0; rl < 5; rl++) {
                #pragma unroll
                for (int i = 0; i < 4; i++)
                    part[(rl * 4 + i) * 36 + lane] = acc[c * 5 + rl][i];
            }
            __syncwarp();
            if (lane < 20) {
                const float4* p4 = (const float4*)(part + lane * 36);
                float4 q0 = p4[0], q1 = p4[1], q2 = p4[2], q3 = p4[3];
                float4 q4 = p4[4], q5 = p4[5], q6 = p4[6], q7 = p4[7];
                float s = ((q0.x + q0.y) + (q0.z + q0.w)) + ((q1.x + q1.y) + (q1.z + q1.w))
                        + ((q2.x + q2.y) + (q2.z + q2.w)) + ((q3.x + q3.y) + (q3.z + q3.w))
                        + ((q4.x + q4.y) + (q4.z + q4.w)) + ((q5.x + q5.y) + (q5.z + q5.w))
                        + ((q6.x + q6.y) + (q6.z + q6.w)) + ((q7.x + q7.y) + (q7.z + q7.w));
                sfw[(lane & 3) * 21 + sub * 10 + c * 5 + (lane >> 2)] = s;
            }
            __syncwarp();
        }

        pair_bar(pair);   // pair's 20 sums visible to both warps

        // --- epilogue: this warp handles tokens {sub*2, sub*2+1} ---
        int e  = lane >> 1;
        int fb = (lane & 1) << 3;
        const float* tb0 = stab + e * TSTRIDE + fb;

        #pragma unroll 1
        for (int i = sub * 2; i < sub * 2 + 2; i++) {
            if (t0 + i >= end) break;
            const float* sf = sfw + i * 21;
            float h0 = fmaxf(sf[16] + smisc[26], 0.f);
            float h1 = fmaxf(sf[17] + smisc[27], 0.f);
            float h2 = fmaxf(sf[18] + smisc[28], 0.f);
            float h3 = fmaxf(sf[19] + smisc[29], 0.f);
            float mu = (h0 * smisc[0] + h1 * smisc[1] + h2 * smisc[2] + h3 * smisc[3]
                        + smisc[24]) * (1.f / 2048.f);
            const float* Q = smisc + 4;
            float ex = smisc[25]
                     + 2.f * (h0 * smisc[20] + h1 * smisc[21] + h2 * smisc[22] + h3 * smisc[23])
                     + h0 * (h0 * Q[0]  + h1 * Q[1]  + h2 * Q[2]  + h3 * Q[3])
                     + h1 * (h0 * Q[4]  + h1 * Q[5]  + h2 * Q[6]  + h3 * Q[7])
                     + h2 * (h0 * Q[8]  + h1 * Q[9]  + h2 * Q[10] + h3 * Q[11])
                     + h3 * (h0 * Q[12] + h1 * Q[13] + h2 * Q[14] + h3 * Q[15]);
            ex *= (1.f / 2048.f);
            float rstd = rsqrtf(ex - mu * mu + 1e-5f);

            float Lv[8];
            float Lmax = -1e30f;
            #pragma unroll
            for (int ff = 0; ff < 8; ff++) {
                float a = tb0[4 * TSIZE + ff];                 // Tb
                a = fmaf(h0, tb0[0 * TSIZE + ff], a);
                a = fmaf(h1, tb0[1 * TSIZE + ff], a);
                a = fmaf(h2, tb0[2 * TSIZE + ff], a);
                a = fmaf(h3, tb0[3 * TSIZE + ff], a);
                a = fmaf(-mu, tb0[5 * TSIZE + ff], a);         // Gs
                float L = fmaf(rstd, a, tb0[6 * TSIZE + ff]);  // Bs
                Lv[ff] = L;
                Lmax = fmaxf(Lmax, L);
            }
            Lmax = fmaxf(Lmax, __shfl_xor_sync(~0u, Lmax, 1));
            float se = 0.f, gd = 0.f;
            #pragma unroll
            for (int ff = 0; ff < 8; ff++) {
                float p = __expf(Lv[ff] - Lmax);
                se += p;
                gd = fmaf(p, sf[fb + ff] + smisc[30 + fb + ff], gd);
            }
            se += __shfl_xor_sync(~0u, se, 1);
            gd += __shfl_xor_sync(~0u, gd, 1);
            float gate = gd / se;

            // rw = softmax over e (parity-preserving butterfly)
            float gmax = gate;
            #pragma unroll
            for (int m = 2; m <= 16; m <<= 1)
                gmax = fmaxf(gmax, __shfl_xor_sync(~0u, gmax, m));
            float er = __expf(gate - gmax);
            float es = er;
            #pragma unroll
            for (int m = 2; m <= 16; m <<= 1)
                es += __shfl_xor_sync(~0u, es, m);
            float rw = er / es;

            // top-2 over e with index tie-break (lower index wins)
            float v1 = rw, v2 = -1.f;
            int i1 = e, i2 = 16;
            #pragma unroll
            for (int m = 2; m <= 16; m <<= 1) {
                float ov1 = __shfl_xor_sync(~0u, v1, m);
                int   oi1 = __shfl_xor_sync(~0u, i1, m);
                float ov2 = __shfl_xor_sync(~0u, v2, m);
                int   oi2 = __shfl_xor_sync(~0u, i2, m);
                bool fw = (v1 > ov1) || (v1 == ov1 && i1 < oi1);
                float w1v = fw ? v1 : ov1;  int w1i = fw ? i1 : oi1;
                float l1v = fw ? ov1 : v1;  int l1i = fw ? oi1 : i1;
                float c2v = fw ? v2 : ov2;  int c2i = fw ? i2 : oi2;
                bool sv = (l1v > c2v) || (l1v == c2v && l1i < c2i);
                v1 = w1v; i1 = w1i;
                v2 = sv ? l1v : c2v;
                i2 = sv ? l1i : c2i;
            }

            float texp = __expf((v2 - v1) * 10.f);
            float inv = 1.f / (1.f + texp);
            float ov = (e == i1) ? inv : ((e == i2) ? texp * inv : 0.f);
            if (!(lane & 1)) out[(size_t)(t0 + i) * 16 + e] = ov;
        }

        pair_bar(pair);   // sums consumed; safe to overwrite next iteration
    }
}

// ---------------------------------------------------------------------------
extern "C" void kernel_launch(void* const* d_in, const int* in_sizes, int n_in,
                              void* d_out, int out_size)
{
    const float* hidden = (const float*)d_in[0];
    const float* ee     = (const float*)d_in[1];
    const float* gamma  = (const float*)d_in[2];
    const float* beta   = (const float*)d_in[3];
    const float* wv_w   = (const float*)d_in[4];
    const float* wv_b   = (const float*)d_in[5];
    const float* w1     = (const float*)d_in[6];
    const float* b1     = (const float*)d_in[7];
    const float* w2     = (const float*)d_in[8];
    const float* b2     = (const float*)d_in[9];
    const float* wq     = (const float*)d_in[10];
    const float* wk     = (const float*)d_in[11];
    float* out = (float*)d_out;

    cudaFuncSetAttribute(fused_kernel, cudaFuncAttributeMaxDynamicSharedMemorySize,
                         SMEM_BYTES);

    fused_kernel<<<GRID, TPB, SMEM_BYTES>>>(hidden, ee, gamma, beta, wv_w, wv_b,
                                            w1, b1, w2, b2, wq, wk, out);
}

// round 8
// speedup vs baseline: 2.1544x; 1.1025x over previous
#include <cuda_runtime.h>
#include <cstdint>
#include <math.h>

// ---------------------------------------------------------------------------
// Hybrid router. B*S=16384 tokens, IN=2048, E=16, D=128, A=128, R=4, top_k=2.
// Single fused kernel, TPB=512 (16 warps = 8 pairs). Per-block prep restructured
// for latency (batched wred, coalesced Mk); main loop: each pair processes 4
// tokens, warp sub=0 rows 0..9 / sub=1 rows 10..19, plain fp32 FMA, hidden via
// direct LDG with 1-iter register prefetch. Tiny per-token epilogue.
// ---------------------------------------------------------------------------

#define NTOK 16384
#define GRID 148
#define TPB  512
#define NWARP 16
#define NPAIR 8

#define TSTRIDE 35
#define TSIZE   544

// smem layout (floats)
#define SW_F      40960            // 20 rows x 2048 weights (16 Wv + 4 w1)
#define STAB_F    (7 * TSIZE)      // 3808
#define SMISC_F   64
#define SFIN_F    (NPAIR * 84)     // per-pair final sums: 4 tok x 21
#define SPART_F   (NWARP * 736)    // per-warp reduce scratch (also prep scratch)
#define OFF_STAB  SW_F
#define OFF_SMISC (OFF_STAB + STAB_F)
#define OFF_SFIN  (OFF_SMISC + SMISC_F)
#define OFF_SPART (OFF_SFIN + SFIN_F)
#define SMEM_FLOATS (OFF_SPART + SPART_F)
#define SMEM_BYTES  (SMEM_FLOATS * 4)

// ---------------------------------------------------------------------------
__device__ __forceinline__ float wred(float v) {
    #pragma unroll
    for (int m = 16; m; m >>= 1) v += __shfl_xor_sync(~0u, v, m);
    return v;
}
__device__ __forceinline__ void pair_bar(int pair) {
    asm volatile("bar.sync %0, 64;" :: "r"(pair + 1) : "memory");
}

// ---------------------------------------------------------------------------
__global__ void __launch_bounds__(TPB, 1)
fused_kernel(const float* __restrict__ hidden, const float* __restrict__ ee,
             const float* __restrict__ gamma, const float* __restrict__ beta,
             const float* __restrict__ wv_w, const float* __restrict__ wv_b,
             const float* __restrict__ w1, const float* __restrict__ b1,
             const float* __restrict__ w2, const float* __restrict__ b2,
             const float* __restrict__ wq, const float* __restrict__ wk,
             float* __restrict__ out)
{
    extern __shared__ float smem[];
    float* sw    = smem;
    float* stab  = smem + OFF_STAB;
    float* smisc = smem + OFF_SMISC;
    float* sfin  = smem + OFF_SFIN;
    float* spart = smem + OFF_SPART;

    int tid = threadIdx.x, lane = tid & 31, warp = tid >> 5;
    int pair = warp >> 1, sub = warp & 1;

    // ===================== stage 0: weights -> smem =====================
    for (int idx = tid; idx < 8192; idx += TPB)
        ((float4*)sw)[idx] = ((const float4*)wv_w)[idx];
    for (int idx = tid; idx < 2048; idx += TPB)
        ((float4*)sw)[8192 + idx] = ((const float4*)w1)[idx];

    // ===================== stage 1: per-block precompute =====================
    float* sge  = spart;           // 2048
    float* sk_  = spart + 2048;    // 2048
    float* sMk  = spart + 4096;    // 2048
    float* sred = sfin;            // scratch (re-used later as per-pair sums)

    // --- LN of expert_embedding over all 2048 ---
    {
        float ls = 0.f, lq = 0.f;
        for (int i = tid; i < 2048; i += TPB) {
            float v = ee[i];
            sge[i] = v; ls += v; lq += v * v;
        }
        ls = wred(ls); lq = wred(lq);
        if (lane == 0) { sred[warp] = ls; sred[16 + warp] = lq; }
        __syncthreads();
        if (tid == 0) {
            float s = 0.f, q = 0.f;
            for (int i = 0; i < NWARP; i++) { s += sred[i]; q += sred[16 + i]; }
            float mu = s * (1.0f / 2048.0f);
            float var = q * (1.0f / 2048.0f) - mu * mu;
            sred[32] = mu; sred[33] = rsqrtf(var + 1e-5f);
        }
        __syncthreads();
        float mu = sred[32], rs = sred[33];
        for (int i = tid; i < 2048; i += TPB)
            sge[i] = (sge[i] - mu) * rs * gamma[i] + beta[i];
        __syncthreads();
    }

    // --- k[f][a] = sum_d ge[f,d]*Wk[a,d]; warp w <-> f=w, 8-output batches so
    //     the 8 wred butterflies interleave (ILP hides SHFL latency) ---
    {
        int f = warp;
        float4 g4 = ((const float4*)(sge + f * 128))[lane];
        #pragma unroll 1
        for (int b = 0; b < 16; b++) {
            float p[8];
            #pragma unroll
            for (int q = 0; q < 8; q++) {
                float4 w4 = ((const float4*)(wk + (b * 8 + q) * 128))[lane];
                p[q] = fmaf(g4.x, w4.x, fmaf(g4.y, w4.y,
                       fmaf(g4.z, w4.z, g4.w * w4.w)));
            }
            #pragma unroll
            for (int m = 16; m; m >>= 1) {
                #pragma unroll
                for (int q = 0; q < 8; q++)
                    p[q] += __shfl_xor_sync(~0u, p[q], m);
            }
            if (lane == 0) {
                #pragma unroll
                for (int q = 0; q < 8; q++) sk_[f * 128 + b * 8 + q] = p[q];
            }
        }
    }
    __syncthreads();

    // --- Mk[f][d] = scale*sum_a k[f,a]*Wq[a,d]; warp w <-> f=w, lanes cover d
    //     (float4), coalesced LDG of wq rows, no cross-lane reduction ---
    {
        int f = warp;
        const float* kf = sk_ + f * 128;
        const float4* wq4 = (const float4*)wq + lane;
        float4 a4 = make_float4(0.f, 0.f, 0.f, 0.f);
        #pragma unroll 8
        for (int a = 0; a < 128; a++) {
            float s = kf[a];
            float4 w4 = wq4[a * 32];
            a4.x = fmaf(s, w4.x, a4.x);
            a4.y = fmaf(s, w4.y, a4.y);
            a4.z = fmaf(s, w4.z, a4.z);
            a4.w = fmaf(s, w4.w, a4.w);
        }
        const float scale = 0.08838834764831845f;  // 1/sqrt(128)
        a4.x *= scale; a4.y *= scale; a4.z *= scale; a4.w *= scale;
        ((float4*)(sMk + f * 128))[lane] = a4;
    }
    __syncthreads();

    // --- tables T0..T3, Tb, Gs, Bs per (e,f): one warp per pair;
    //     the 7 wred chains are independent (ILP) ---
    for (int pr = warp; pr < 256; pr += NWARP) {
        int e = pr >> 4, f = pr & 15;
        int o = e * 128 + lane * 4;
        float4 mk = ((const float4*)(sMk + f * 128))[lane];
        float4 ga = *(const float4*)(gamma + o);
        float4 be = *(const float4*)(beta + o);
        float4 bb = *(const float4*)(b2 + o);
        float4 wA = *(const float4*)(w2 + (o + 0) * 4);
        float4 wB = *(const float4*)(w2 + (o + 1) * 4);
        float4 wC = *(const float4*)(w2 + (o + 2) * 4);
        float4 wD = *(const float4*)(w2 + (o + 3) * 4);
        float m0 = mk.x * ga.x, m1 = mk.y * ga.y, m2 = mk.z * ga.z, m3 = mk.w * ga.w;
        float t0 = m0 * wA.x + m1 * wB.x + m2 * wC.x + m3 * wD.x;
        float t1 = m0 * wA.y + m1 * wB.y + m2 * wC.y + m3 * wD.y;
        float t2 = m0 * wA.z + m1 * wB.z + m2 * wC.z + m3 * wD.z;
        float t3 = m0 * wA.w + m1 * wB.w + m2 * wC.w + m3 * wD.w;
        float tb = m0 * bb.x + m1 * bb.y + m2 * bb.z + m3 * bb.w;
        float gs = m0 + m1 + m2 + m3;
        float bs = mk.x * be.x + mk.y * be.y + mk.z * be.z + mk.w * be.w;
        #pragma unroll
        for (int m = 16; m; m >>= 1) {
            t0 += __shfl_xor_sync(~0u, t0, m);
            t1 += __shfl_xor_sync(~0u, t1, m);
            t2 += __shfl_xor_sync(~0u, t2, m);
            t3 += __shfl_xor_sync(~0u, t3, m);
            tb += __shfl_xor_sync(~0u, tb, m);
            gs += __shfl_xor_sync(~0u, gs, m);
            bs += __shfl_xor_sync(~0u, bs, m);
        }
        if (lane == 0) {
            int oo = e * TSTRIDE + f;
            stab[0 * TSIZE + oo] = t0;
            stab[1 * TSIZE + oo] = t1;
            stab[2 * TSIZE + oo] = t2;
            stab[3 * TSIZE + oo] = t3;
            stab[4 * TSIZE + oo] = tb;
            stab[5 * TSIZE + oo] = gs;
            stab[6 * TSIZE + oo] = bs;
        }
    }
    __syncthreads();

    // --- rank-4 moments of dyn: S1[4], Q[16], C[4], S0, SSB ---
    {
        float p[26];
        #pragma unroll
        for (int q = 0; q < 26; q++) p[q] = 0.f;
        for (int o = tid; o < 2048; o += TPB) {
            float4 w4 = *(const float4*)(w2 + o * 4);
            float b = b2[o];
            float w0v = w4.x, w1v = w4.y, w2v = w4.z, w3v = w4.w;
            p[0] += w0v; p[1] += w1v; p[2] += w2v; p[3] += w3v;
            p[4]  += w0v * w0v; p[5]  += w0v * w1v; p[6]  += w0v * w2v; p[7]  += w0v * w3v;
            p[8]  += w1v * w0v; p[9]  += w1v * w1v; p[10] += w1v * w2v; p[11] += w1v * w3v;
            p[12] += w2v * w0v; p[13] += w2v * w1v; p[14] += w2v * w2v; p[15] += w2v * w3v;
            p[16] += w3v * w0v; p[17] += w3v * w1v; p[18] += w3v * w2v; p[19] += w3v * w3v;
            p[20] += w0v * b; p[21] += w1v * b; p[22] += w2v * b; p[23] += w3v * b;
            p[24] += b; p[25] += b * b;
        }
        #pragma unroll
        for (int q = 0; q < 26; q++) p[q] = wred(p[q]);
        if (lane == 0) {
            #pragma unroll
            for (int q = 0; q < 26; q++) sred[warp * 26 + q] = p[q];
        }
        __syncthreads();
        if (tid < 26) {
            float s = 0.f;
            for (int w = 0; w < NWARP; w++) s += sred[w * 26 + tid];
            smisc[tid] = s;
        }
        __syncthreads();
        if (tid < 4)  smisc[26 + tid] = b1[tid];
        if (tid < 16) smisc[30 + tid] = wv_b[tid];
        __syncthreads();
    }

    // ===================== stage 2: token stream =====================
    int start = (int)(((long long)blockIdx.x * NTOK) / GRID);
    int end   = (int)(((long long)(blockIdx.x + 1) * NTOK) / GRID);

    float* part = spart + warp * 736;     // per-warp transpose scratch (720 used)
    float* sfw  = sfin + pair * 84;       // per-pair sums: [4 tok][21]
    const float* swr = sw + sub * 10 * 2048;  // this warp's 10 rows

    for (int t0 = start + pair * 4; t0 < end; t0 += NPAIR * 4) {
        const char* gp[4];
        #pragma unroll
        for (int i = 0; i < 4; i++) {
            int tt = t0 + i;
            if (tt > NTOK - 1) tt = NTOK - 1;
            gp[i] = (const char*)(hidden + (size_t)tt * 2048) + lane * 16;
        }

        float acc[10][4];
        #pragma unroll
        for (int r = 0; r < 10; r++)
            #pragma unroll
            for (int i = 0; i < 4; i++) acc[r][i] = 0.f;

        float4 nhv[4];
        #pragma unroll
        for (int i = 0; i < 4; i++) nhv[i] = *(const float4*)gp[i];

        #pragma unroll 1
        for (int j = 0; j < 16; j++) {
            float4 hv[4];
            #pragma unroll
            for (int i = 0; i < 4; i++) hv[i] = nhv[i];
            if (j < 15) {
                #pragma unroll
                for (int i = 0; i < 4; i++)
                    nhv[i] = *(const float4*)(gp[i] + (j + 1) * 512);
            }
            const float4* wj = (const float4*)(swr + j * 128) + lane;
            #pragma unroll
            for (int r = 0; r < 10; r++) {
                float4 wv = wj[r * 512];
                #pragma unroll
                for (int i = 0; i < 4; i++) {
                    acc[r][i] = fmaf(hv[i].x, wv.x, acc[r][i]);
                    acc[r][i] = fmaf(hv[i].y, wv.y, acc[r][i]);
                    acc[r][i] = fmaf(hv[i].z, wv.z, acc[r][i]);
                    acc[r][i] = fmaf(hv[i].w, wv.w, acc[r][i]);
                }
            }
        }

        // --- chunked smem-transpose reduction: 2 chunks of 5 rows ---
        #pragma unroll
        for (int c = 0; c < 2; c++) {
            #pragma unroll
            for (int rl = 0; rl < 5; rl++) {
                #pragma unroll
                for (int i = 0; i < 4; i++)
                    part[(rl * 4 + i) * 36 + lane] = acc[c * 5 + rl][i];
            }
            __syncwarp();
            if (lane < 20) {
                const float4* p4 = (const float4*)(part + lane * 36);
                float4 q0 = p4[0], q1 = p4[1], q2 = p4[2], q3 = p4[3];
                float4 q4 = p4[4], q5 = p4[5], q6 = p4[6], q7 = p4[7];
                float s = ((q0.x + q0.y) + (q0.z + q0.w)) + ((q1.x + q1.y) + (q1.z + q1.w))
                        + ((q2.x + q2.y) + (q2.z + q2.w)) + ((q3.x + q3.y) + (q3.z + q3.w))
                        + ((q4.x + q4.y) + (q4.z + q4.w)) + ((q5.x + q5.y) + (q5.z + q5.w))
                        + ((q6.x + q6.y) + (q6.z + q6.w)) + ((q7.x + q7.y) + (q7.z + q7.w));
                sfw[(lane & 3) * 21 + sub * 10 + c * 5 + (lane >> 2)] = s;
            }
            __syncwarp();
        }

        pair_bar(pair);   // pair's 20 sums visible to both warps

        // --- epilogue: this warp handles tokens {sub*2, sub*2+1} ---
        int e  = lane >> 1;
        int fb = (lane & 1) << 3;
        const float* tb0 = stab + e * TSTRIDE + fb;

        #pragma unroll 1
        for (int i = sub * 2; i < sub * 2 + 2; i++) {
            if (t0 + i >= end) break;
            const float* sf = sfw + i * 21;
            float h0 = fmaxf(sf[16] + smisc[26], 0.f);
            float h1 = fmaxf(sf[17] + smisc[27], 0.f);
            float h2 = fmaxf(sf[18] + smisc[28], 0.f);
            float h3 = fmaxf(sf[19] + smisc[29], 0.f);
            float mu = (h0 * smisc[0] + h1 * smisc[1] + h2 * smisc[2] + h3 * smisc[3]
                        + smisc[24]) * (1.f / 2048.f);
            const float* Q = smisc + 4;
            float ex = smisc[25]
                     + 2.f * (h0 * smisc[20] + h1 * smisc[21] + h2 * smisc[22] + h3 * smisc[23])
                     + h0 * (h0 * Q[0]  + h1 * Q[1]  + h2 * Q[2]  + h3 * Q[3])
                     + h1 * (h0 * Q[4]  + h1 * Q[5]  + h2 * Q[6]  + h3 * Q[7])
                     + h2 * (h0 * Q[8]  + h1 * Q[9]  + h2 * Q[10] + h3 * Q[11])
                     + h3 * (h0 * Q[12] + h1 * Q[13] + h2 * Q[14] + h3 * Q[15]);
            ex *= (1.f / 2048.f);
            float rstd = rsqrtf(ex - mu * mu + 1e-5f);

            float Lv[8];
            float Lmax = -1e30f;
            #pragma unroll
            for (int ff = 0; ff < 8; ff++) {
                float a = tb0[4 * TSIZE + ff];                 // Tb
                a = fmaf(h0, tb0[0 * TSIZE + ff], a);
                a = fmaf(h1, tb0[1 * TSIZE + ff], a);
                a = fmaf(h2, tb0[2 * TSIZE + ff], a);
                a = fmaf(h3, tb0[3 * TSIZE + ff], a);
                a = fmaf(-mu, tb0[5 * TSIZE + ff], a);         // Gs
                float L = fmaf(rstd, a, tb0[6 * TSIZE + ff]);  // Bs
                Lv[ff] = L;
                Lmax = fmaxf(Lmax, L);
            }
            Lmax = fmaxf(Lmax, __shfl_xor_sync(~0u, Lmax, 1));
            float se = 0.f, gd = 0.f;
            #pragma unroll
            for (int ff = 0; ff < 8; ff++) {
                float p = __expf(Lv[ff] - Lmax);
                se += p;
                gd = fmaf(p, sf[fb + ff] + smisc[30 + fb + ff], gd);
            }
            se += __shfl_xor_sync(~0u, se, 1);
            gd += __shfl_xor_sync(~0u, gd, 1);
            float gate = gd / se;

            // rw = softmax over e (parity-preserving butterfly)
            float gmax = gate;
            #pragma unroll
            for (int m = 2; m <= 16; m <<= 1)
                gmax = fmaxf(gmax, __shfl_xor_sync(~0u, gmax, m));
            float er = __expf(gate - gmax);
            float es = er;
            #pragma unroll
            for (int m = 2; m <= 16; m <<= 1)
                es += __shfl_xor_sync(~0u, es, m);
            float rw = er / es;

            // top-2 over e with index tie-break (lower index wins)
            float v1 = rw, v2 = -1.f;
            int i1 = e, i2 = 16;
            #pragma unroll
            for (int m = 2; m <= 16; m <<= 1) {
                float ov1 = __shfl_xor_sync(~0u, v1, m);
                int   oi1 = __shfl_xor_sync(~0u, i1, m);
                float ov2 = __shfl_xor_sync(~0u, v2, m);
                int   oi2 = __shfl_xor_sync(~0u, i2, m);
                bool fw = (v1 > ov1) || (v1 == ov1 && i1 < oi1);
                float w1v = fw ? v1 : ov1;  int w1i = fw ? i1 : oi1;
                float l1v = fw ? ov1 : v1;  int l1i = fw ? oi1 : i1;
                float c2v = fw ? v2 : ov2;  int c2i = fw ? i2 : oi2;
                bool sv = (l1v > c2v) || (l1v == c2v && l1i < c2i);
                v1 = w1v; i1 = w1i;
                v2 = sv ? l1v : c2v;
                i2 = sv ? l1i : c2i;
            }

            float texp = __expf((v2 - v1) * 10.f);
            float inv = 1.f / (1.f + texp);
            float ov = (e == i1) ? inv : ((e == i2) ? texp * inv : 0.f);
            if (!(lane & 1)) out[(size_t)(t0 + i) * 16 + e] = ov;
        }

        pair_bar(pair);   // sums consumed; safe to overwrite next iteration
    }
}

// ---------------------------------------------------------------------------
extern "C" void kernel_launch(void* const* d_in, const int* in_sizes, int n_in,
                              void* d_out, int out_size)
{
    const float* hidden = (const float*)d_in[0];
    const float* ee     = (const float*)d_in[1];
    const float* gamma  = (const float*)d_in[2];
    const float* beta   = (const float*)d_in[3];
    const float* wv_w   = (const float*)d_in[4];
    const float* wv_b   = (const float*)d_in[5];
    const float* w1     = (const float*)d_in[6];
    const float* b1     = (const float*)d_in[7];
    const float* w2     = (const float*)d_in[8];
    const float* b2     = (const float*)d_in[9];
    const float* wq     = (const float*)d_in[10];
    const float* wk     = (const float*)d_in[11];
    float* out = (float*)d_out;

    cudaFuncSetAttribute(fused_kernel, cudaFuncAttributeMaxDynamicSharedMemorySize,
                         SMEM_BYTES);

    fused_kernel<<<GRID, TPB, SMEM_BYTES>>>(hidden, ee, gamma, beta, wv_w, wv_b,
                                            w1, b1, w2, b2, wq, wk, out);
}